// round 6
// baseline (speedup 1.0000x reference)
#include <cuda_runtime.h>
#include <cstdint>

#define Bsz 256
#define Tsz 128
#define Fsz 256
#define Hsz 512
#define Csz 10

// Scratch: proj/h buffers, written in place by the recurrence.
__device__ float g_buf0[Bsz * Tsz * Hsz];   // 64 MB
__device__ float g_buf1[Bsz * Tsz * Hsz];   // 64 MB

// Grid-barrier state for the persistent recurrence kernels.
__device__ unsigned g_count;   // zero-init; returns to 0 after every completed barrier
__device__ unsigned g_sense;   // monotonically increasing generation

// ---------------------------------------------------------------------------
// Projection GEMM: out[m, n] = sum_k A[m, k] * Wt[n, k] + bias1[n] + bias2[n]
// M = 32768, N = 512, K in {256, 512}.
// Tiles: BM=128, BN=64, BK=8. 256 threads, each computes 8x4.
// ---------------------------------------------------------------------------
__global__ void __launch_bounds__(256) proj_gemm(
    const float* __restrict__ A, const float* __restrict__ Wt,
    const float* __restrict__ bias1, const float* __restrict__ bias2,
    float* __restrict__ out, int K)
{
    __shared__ float As[8][128];
    __shared__ float Bs[8][64];

    const int tid = threadIdx.x;
    const int m0 = blockIdx.y * 128;
    const int n0 = blockIdx.x * 64;
    const int tx = tid & 15;         // 0..15 -> 4 output cols
    const int ty = tid >> 4;         // 0..15 -> 8 output rows

    const int arow  = tid >> 1;      // 0..127
    const int ahalf = tid & 1;       // 0/1 (which float4 of the 8-wide k-slab)
    const float* ap = A + (size_t)(m0 + arow) * K + ahalf * 4;
    const int brow  = (tid < 128) ? (tid >> 1) : 0;   // 0..63
    const float* bp = Wt + (size_t)(n0 + brow) * K + ahalf * 4;

    float acc[8][4];
#pragma unroll
    for (int i = 0; i < 8; ++i)
#pragma unroll
        for (int jj = 0; jj < 4; ++jj) acc[i][jj] = 0.f;

    float4 ra = *reinterpret_cast<const float4*>(ap);
    float4 rb = (tid < 128) ? *reinterpret_cast<const float4*>(bp)
                            : make_float4(0.f, 0.f, 0.f, 0.f);

    const int S = K >> 3;
    for (int s = 0; s < S; ++s) {
        // Store current stage registers -> smem
        As[ahalf * 4 + 0][arow] = ra.x;
        As[ahalf * 4 + 1][arow] = ra.y;
        As[ahalf * 4 + 2][arow] = ra.z;
        As[ahalf * 4 + 3][arow] = ra.w;
        if (tid < 128) {
            Bs[ahalf * 4 + 0][brow] = rb.x;
            Bs[ahalf * 4 + 1][brow] = rb.y;
            Bs[ahalf * 4 + 2][brow] = rb.z;
            Bs[ahalf * 4 + 3][brow] = rb.w;
        }
        __syncthreads();

        // Prefetch next stage into registers while computing this one.
        if (s + 1 < S) {
            ra = *reinterpret_cast<const float4*>(ap + (size_t)(s + 1) * 8);
            if (tid < 128)
                rb = *reinterpret_cast<const float4*>(bp + (size_t)(s + 1) * 8);
        }

#pragma unroll
        for (int k = 0; k < 8; ++k) {
            float4 b4 = *reinterpret_cast<const float4*>(&Bs[k][tx * 4]);
            float4 a0 = *reinterpret_cast<const float4*>(&As[k][ty * 8]);
            float4 a1 = *reinterpret_cast<const float4*>(&As[k][ty * 8 + 4]);
            float av[8] = {a0.x, a0.y, a0.z, a0.w, a1.x, a1.y, a1.z, a1.w};
            float bv[4] = {b4.x, b4.y, b4.z, b4.w};
#pragma unroll
            for (int i = 0; i < 8; ++i)
#pragma unroll
                for (int jj = 0; jj < 4; ++jj)
                    acc[i][jj] = fmaf(av[i], bv[jj], acc[i][jj]);
        }
        __syncthreads();
    }

    float bb[4];
#pragma unroll
    for (int jj = 0; jj < 4; ++jj)
        bb[jj] = bias1[n0 + tx * 4 + jj] + bias2[n0 + tx * 4 + jj];

#pragma unroll
    for (int i = 0; i < 8; ++i) {
        float4 v = make_float4(acc[i][0] + bb[0], acc[i][1] + bb[1],
                               acc[i][2] + bb[2], acc[i][3] + bb[3]);
        *reinterpret_cast<float4*>(out + (size_t)(m0 + ty * 8 + i) * Hsz + n0 + tx * 4) = v;
    }
}

// ---------------------------------------------------------------------------
// Persistent recurrence kernel. 128 CTAs x 256 threads, all co-resident.
// buf holds proj[B,T,H] on entry; h_t is written in place over proj[:,t,:].
// Tile: 32 batch rows x 32 hidden cols per CTA. W^T tile persistent in smem.
// ---------------------------------------------------------------------------
#define REC_NBLK 128
#define REC_WPITCH 34   // pitch (floats) for W^T smem: conflict-free + 8B aligned
#define REC_SMEM_BYTES ((Hsz * REC_WPITCH + 32 * Hsz) * 4)

__device__ __forceinline__ void grid_barrier(unsigned& gen)
{
    __syncthreads();
    if (threadIdx.x == 0) {
        __threadfence();
        unsigned arrived = atomicAdd(&g_count, 1u);
        gen++;
        if (arrived == REC_NBLK - 1) {
            atomicExch(&g_count, 0u);
            __threadfence();
            atomicAdd(&g_sense, 1u);
        } else {
            while ((int)(*(volatile unsigned*)&g_sense - gen) < 0) { }
        }
        __threadfence();
    }
    __syncthreads();
}

__global__ void __launch_bounds__(256) rnn_rec(
    float* __restrict__ buf, const float* __restrict__ Whh)
{
    extern __shared__ float sm[];
    float* WsT = sm;                        // [512][REC_WPITCH]: W^T for this col tile
    float* Ash = sm + Hsz * REC_WPITCH;     // [32][512]: h_{t-1} rows for this row tile

    const int tid = threadIdx.x;
    const int tile_m = blockIdx.x >> 4;     // 0..7   -> batch rows
    const int tile_n = blockIdx.x & 15;     // 0..15  -> hidden cols
    const int b0 = tile_m * 32;
    const int n0 = tile_n * 32;

    // Load this tile's 32 columns of W_hh, transposed, once for all 128 steps.
    for (int i = tid; i < 32 * Hsz; i += 256) {
        int jj = i >> 9;       // 0..31 col within tile
        int k  = i & 511;
        WsT[k * REC_WPITCH + jj] = Whh[(size_t)(n0 + jj) * Hsz + k];
    }

    unsigned gen = 0;
    if (tid == 0) gen = *(volatile unsigned*)&g_sense;   // barrier generation base

    const int j = (tid & 15) * 2;   // 2 cols per thread
    const int r = (tid >> 4) * 2;   // 2 rows per thread

    // t = 0: h_0 = relu(proj_0)  (h_{-1} = 0)
#pragma unroll
    for (int rr = 0; rr < 2; ++rr) {
        float* p = buf + ((size_t)(b0 + r + rr) * Tsz + 0) * Hsz + n0 + j;
        float2 v = *reinterpret_cast<float2*>(p);
        v.x = fmaxf(v.x, 0.f);
        v.y = fmaxf(v.y, 0.f);
        *reinterpret_cast<float2*>(p) = v;
    }
    __threadfence();

    for (int t = 1; t < Tsz; ++t) {
        grid_barrier(gen);   // all h_{t-1} writes visible; also guards Ash reuse

        // Stage h_{t-1} rows b0..b0+31 into smem (coalesced float4).
        for (int i = tid; i < 32 * 128; i += 256) {
            int rr = i >> 7;
            int c  = (i & 127) * 4;
            float4 v = *reinterpret_cast<const float4*>(
                buf + ((size_t)(b0 + rr) * Tsz + (t - 1)) * Hsz + c);
            *reinterpret_cast<float4*>(Ash + rr * Hsz + c) = v;
        }
        __syncthreads();

        const float* Ar0 = Ash + r * Hsz;
        const float* Ar1 = Ar0 + Hsz;
        float a00 = 0.f, a01 = 0.f, a10 = 0.f, a11 = 0.f;
#pragma unroll 4
        for (int k = 0; k < Hsz; k += 4) {
            float4 x0 = *reinterpret_cast<const float4*>(Ar0 + k);
            float4 x1 = *reinterpret_cast<const float4*>(Ar1 + k);
            float2 w0 = *reinterpret_cast<const float2*>(WsT + (k + 0) * REC_WPITCH + j);
            float2 w1 = *reinterpret_cast<const float2*>(WsT + (k + 1) * REC_WPITCH + j);
            float2 w2 = *reinterpret_cast<const float2*>(WsT + (k + 2) * REC_WPITCH + j);
            float2 w3 = *reinterpret_cast<const float2*>(WsT + (k + 3) * REC_WPITCH + j);
            a00 = fmaf(x0.x, w0.x, a00); a01 = fmaf(x0.x, w0.y, a01);
            a10 = fmaf(x1.x, w0.x, a10); a11 = fmaf(x1.x, w0.y, a11);
            a00 = fmaf(x0.y, w1.x, a00); a01 = fmaf(x0.y, w1.y, a01);
            a10 = fmaf(x1.y, w1.x, a10); a11 = fmaf(x1.y, w1.y, a11);
            a00 = fmaf(x0.z, w2.x, a00); a01 = fmaf(x0.z, w2.y, a01);
            a10 = fmaf(x1.z, w2.x, a10); a11 = fmaf(x1.z, w2.y, a11);
            a00 = fmaf(x0.w, w3.x, a00); a01 = fmaf(x0.w, w3.y, a01);
            a10 = fmaf(x1.w, w3.x, a10); a11 = fmaf(x1.w, w3.y, a11);
        }

        // h_t = relu(proj_t + h_{t-1} @ W^T), written in place.
        float* p0 = buf + ((size_t)(b0 + r) * Tsz + t) * Hsz + n0 + j;
        float* p1 = buf + ((size_t)(b0 + r + 1) * Tsz + t) * Hsz + n0 + j;
        float2 q0 = *reinterpret_cast<float2*>(p0);
        float2 q1 = *reinterpret_cast<float2*>(p1);
        float2 o0 = make_float2(fmaxf(q0.x + a00, 0.f), fmaxf(q0.y + a01, 0.f));
        float2 o1 = make_float2(fmaxf(q1.x + a10, 0.f), fmaxf(q1.y + a11, 0.f));
        *reinterpret_cast<float2*>(p0) = o0;
        *reinterpret_cast<float2*>(p1) = o1;
        __threadfence();
    }
}

// ---------------------------------------------------------------------------
// Final FC: out[b, c] = sum_i flat[b, i] * Wfc[c, i] + bfc[c]
// One CTA per batch row; 10 accumulators per thread; shuffle + smem reduce.
// ---------------------------------------------------------------------------
__global__ void __launch_bounds__(256) fc_kernel(
    const float* __restrict__ flat, const float* __restrict__ Wfc,
    const float* __restrict__ bfc, float* __restrict__ out)
{
    const int b = blockIdx.x;
    const float* xr = flat + (size_t)b * (Tsz * Hsz);

    float acc[Csz];
#pragma unroll
    for (int c = 0; c < Csz; ++c) acc[c] = 0.f;

    for (int i = threadIdx.x * 4; i < Tsz * Hsz; i += 256 * 4) {
        float4 x = *reinterpret_cast<const float4*>(xr + i);
#pragma unroll
        for (int c = 0; c < Csz; ++c) {
            float4 w = *reinterpret_cast<const float4*>(Wfc + (size_t)c * (Tsz * Hsz) + i);
            acc[c] += x.x * w.x + x.y * w.y + x.z * w.z + x.w * w.w;
        }
    }

#pragma unroll
    for (int c = 0; c < Csz; ++c)
#pragma unroll
        for (int off = 16; off > 0; off >>= 1)
            acc[c] += __shfl_down_sync(0xffffffffu, acc[c], off);

    __shared__ float part[Csz][8];
    const int warp = threadIdx.x >> 5;
    const int lane = threadIdx.x & 31;
    if (lane == 0) {
#pragma unroll
        for (int c = 0; c < Csz; ++c) part[c][warp] = acc[c];
    }
    __syncthreads();
    if (threadIdx.x < Csz) {
        float s = 0.f;
#pragma unroll
        for (int w = 0; w < 8; ++w) s += part[threadIdx.x][w];
        out[b * Csz + threadIdx.x] = s + bfc[threadIdx.x];
    }
}

// ---------------------------------------------------------------------------
// kernel_launch: proj0 -> rec0 -> proj1 -> rec1 -> fc  (all default stream)
// ---------------------------------------------------------------------------
extern "C" void kernel_launch(void* const* d_in, const int* in_sizes, int n_in,
                              void* d_out, int out_size)
{
    (void)in_sizes; (void)n_in; (void)out_size;
    const float* x     = (const float*)d_in[0];
    const float* W_ih0 = (const float*)d_in[1];
    const float* W_hh0 = (const float*)d_in[2];
    const float* b_ih0 = (const float*)d_in[3];
    const float* b_hh0 = (const float*)d_in[4];
    const float* W_ih1 = (const float*)d_in[5];
    const float* W_hh1 = (const float*)d_in[6];
    const float* b_ih1 = (const float*)d_in[7];
    const float* b_hh1 = (const float*)d_in[8];
    const float* W_fc  = (const float*)d_in[9];
    const float* b_fc  = (const float*)d_in[10];
    float* out = (float*)d_out;

    float* buf0 = nullptr;
    float* buf1 = nullptr;
    cudaGetSymbolAddress((void**)&buf0, g_buf0);
    cudaGetSymbolAddress((void**)&buf1, g_buf1);

    cudaFuncSetAttribute(rnn_rec, cudaFuncAttributeMaxDynamicSharedMemorySize,
                         REC_SMEM_BYTES);

    dim3 pgrid(Hsz / 64, (Bsz * Tsz) / 128);   // (8, 256)

    // Layer 0
    proj_gemm<<<pgrid, 256>>>(x, W_ih0, b_ih0, b_hh0, buf0, Fsz);
    rnn_rec<<<REC_NBLK, 256, REC_SMEM_BYTES>>>(buf0, W_hh0);

    // Layer 1
    proj_gemm<<<pgrid, 256>>>(buf0, W_ih1, b_ih1, b_hh1, buf1, Hsz);
    rnn_rec<<<REC_NBLK, 256, REC_SMEM_BYTES>>>(buf1, W_hh1);

    // Classifier
    fc_kernel<<<Bsz, 256>>>(buf1, W_fc, b_fc, out);
}

// round 7
// speedup vs baseline: 1.0412x; 1.0412x over previous
#include <cuda_runtime.h>
#include <cstdint>

#define Bsz 256
#define Tsz 128
#define Fsz 256
#define Hsz 512
#define Csz 10

// Scratch: proj/h buffers, written in place by the recurrence.
__device__ float g_buf0[Bsz * Tsz * Hsz];   // 64 MB
__device__ float g_buf1[Bsz * Tsz * Hsz];   // 64 MB

// Grid-barrier state for the persistent recurrence kernels.
__device__ unsigned g_count;
__device__ unsigned g_sense;

// ---------------------------------------------------------------------------
// f32x2 packed FMA helpers (Blackwell FFMA2 — only reachable via PTX).
// Accumulators are k-paired: .lo sums even-k products, .hi odd-k products.
// ---------------------------------------------------------------------------
__device__ __forceinline__ unsigned long long ffma2(
    unsigned long long a, unsigned long long b, unsigned long long c)
{
    unsigned long long d;
    asm("fma.rn.f32x2 %0, %1, %2, %3;" : "=l"(d) : "l"(a), "l"(b), "l"(c));
    return d;
}
__device__ __forceinline__ float f2sum(unsigned long long v)
{
    float lo, hi;
    asm("mov.b64 {%0, %1}, %2;" : "=f"(lo), "=f"(hi) : "l"(v));
    return lo + hi;
}

// ---------------------------------------------------------------------------
// Projection GEMM: out[m,n] = sum_k A[m,k] * Wt[n,k] + bias1[n] + bias2[n]
// M = 32768, N = 512, K in {256, 512}.
// BM=128, BN=64, BK=16, 256 threads, microtile 8 rows x 4 cols, f32x2 accs.
// Smem is k-contiguous: As[row][k] pitch 20, Bs[col][k] pitch 20.
//   - A-reads: lanes 0-15 share an address -> broadcast.
//   - B-reads: cols tx + 16c; bank = 20*tx mod 32 = {0,20,8,28,16,4,24,12}
//     for tx 0..7 -> conflict-free per LDS.128 phase. pitch*4 = 80B, 16B-aligned.
// ---------------------------------------------------------------------------
#define PJ_BM 128
#define PJ_BN 64
#define PJ_BK 16
#define PJ_PA 20
#define PJ_PB 20

__global__ void __launch_bounds__(256, 2) proj_gemm(
    const float* __restrict__ A, const float* __restrict__ Wt,
    const float* __restrict__ bias1, const float* __restrict__ bias2,
    float* __restrict__ out, int K)
{
    __shared__ float As[PJ_BM * PJ_PA];   // 10.24 KB
    __shared__ float Bs[PJ_BN * PJ_PB];   //  5.12 KB

    const int tid = threadIdx.x;
    const int m0 = blockIdx.y * PJ_BM;
    const int n0 = blockIdx.x * PJ_BN;
    const int tx = tid & 15;          // -> cols tx + 16c, c = 0..3
    const int ty = tid >> 4;          // -> rows ty*8 + i, i = 0..7

    // Global staging assignments (float4 = 4 consecutive k).
    // A: 512 float4/stage, 2 per thread. row = idx>>2, kchunk = idx&3.
    const int arow = tid >> 2;        // 0..63 ; second load uses arow+64
    const int ach  = tid & 3;
    const float* apg = A + (size_t)(m0 + arow) * K + ach * 4;
    // B: 256 float4/stage, 1 per thread.
    const int bcol = tid >> 2;        // 0..63
    const float* bpg = Wt + (size_t)(n0 + bcol) * K + ach * 4;

    unsigned long long acc[8][4];
#pragma unroll
    for (int i = 0; i < 8; ++i)
#pragma unroll
        for (int c = 0; c < 4; ++c) acc[i][c] = 0ull;

    float4 ra0 = *reinterpret_cast<const float4*>(apg);
    float4 ra1 = *reinterpret_cast<const float4*>(apg + (size_t)64 * K);
    float4 rb  = *reinterpret_cast<const float4*>(bpg);

    const int S = K / PJ_BK;
    for (int s = 0; s < S; ++s) {
        // Registers -> smem (k-contiguous layout).
        *reinterpret_cast<float4*>(&As[arow * PJ_PA + ach * 4])        = ra0;
        *reinterpret_cast<float4*>(&As[(arow + 64) * PJ_PA + ach * 4]) = ra1;
        *reinterpret_cast<float4*>(&Bs[bcol * PJ_PB + ach * 4])        = rb;
        __syncthreads();

        if (s + 1 < S) {
            const size_t off = (size_t)(s + 1) * PJ_BK;
            ra0 = *reinterpret_cast<const float4*>(apg + off);
            ra1 = *reinterpret_cast<const float4*>(apg + (size_t)64 * K + off);
            rb  = *reinterpret_cast<const float4*>(bpg + off);
        }

#pragma unroll
        for (int kk = 0; kk < PJ_BK; kk += 4) {
            ulonglong2 bv[4];
#pragma unroll
            for (int c = 0; c < 4; ++c)
                bv[c] = *reinterpret_cast<const ulonglong2*>(
                    &Bs[(tx + c * 16) * PJ_PB + kk]);
#pragma unroll
            for (int i = 0; i < 8; ++i) {
                ulonglong2 av = *reinterpret_cast<const ulonglong2*>(
                    &As[(ty * 8 + i) * PJ_PA + kk]);
#pragma unroll
                for (int c = 0; c < 4; ++c) {
                    acc[i][c] = ffma2(av.x, bv[c].x, acc[i][c]);
                    acc[i][c] = ffma2(av.y, bv[c].y, acc[i][c]);
                }
            }
        }
        __syncthreads();
    }

    float bb[4];
#pragma unroll
    for (int c = 0; c < 4; ++c)
        bb[c] = bias1[n0 + tx + c * 16] + bias2[n0 + tx + c * 16];

#pragma unroll
    for (int i = 0; i < 8; ++i) {
        float* orow = out + (size_t)(m0 + ty * 8 + i) * Hsz + n0 + tx;
#pragma unroll
        for (int c = 0; c < 4; ++c)
            orow[c * 16] = f2sum(acc[i][c]) + bb[c];
    }
}

// ---------------------------------------------------------------------------
// Persistent recurrence. 128 CTAs x 256 threads, all co-resident (1/SM).
// Tile 32 batch rows x 32 hidden cols. Microtile 4 rows x 1 col (col = lane).
// W tile resident in smem for all 128 steps as WsT[col][k], pitch 516
// (2064B rows: 16B-aligned, bank = (4*col + k) % 32 -> conflict-free).
// h_{t-1} rows staged to Ash[32][512] each step (x reads are warp-broadcast).
// ---------------------------------------------------------------------------
#define REC_NBLK 128
#define REC_P 516
#define REC_SMEM_BYTES ((32 * REC_P + 32 * Hsz) * 4)   // 131584 B

__device__ __forceinline__ void grid_barrier(unsigned& gen)
{
    __syncthreads();
    if (threadIdx.x == 0) {
        __threadfence();   // publishes whole CTA's prior global writes (cumulative)
        unsigned arrived = atomicAdd(&g_count, 1u);
        gen++;
        if (arrived == REC_NBLK - 1) {
            atomicExch(&g_count, 0u);
            __threadfence();
            atomicAdd(&g_sense, 1u);
        } else {
            while ((int)(*(volatile unsigned*)&g_sense - gen) < 0) { }
        }
        __threadfence();
    }
    __syncthreads();
}

__global__ void __launch_bounds__(256) rnn_rec(
    float* __restrict__ buf, const float* __restrict__ Whh)
{
    extern __shared__ float sm[];
    float* WsT = sm;                 // [32][REC_P]
    float* Ash = sm + 32 * REC_P;    // [32][512]

    const int tid = threadIdx.x;
    const int tile_m = blockIdx.x >> 4;     // 0..7  batch rows
    const int tile_n = blockIdx.x & 15;     // 0..15 hidden cols
    const int b0 = tile_m * 32;
    const int n0 = tile_n * 32;

    // Load the 32 W_hh rows for this col tile once (row n of W_hh IS col n's k-vector).
    for (int i = tid; i < 32 * 128; i += 256) {
        int jj = i >> 7;
        int kc = (i & 127) * 4;
        float4 v = *reinterpret_cast<const float4*>(
            Whh + (size_t)(n0 + jj) * Hsz + kc);
        *reinterpret_cast<float4*>(WsT + jj * REC_P + kc) = v;
    }

    unsigned gen = 0;
    if (tid == 0) gen = *(volatile unsigned*)&g_sense;

    const int j  = tid & 31;          // col within tile (= lane)
    const int r0 = (tid >> 5) * 4;    // 4 rows per thread

    // t = 0: h_0 = relu(proj_0)
#pragma unroll
    for (int i = 0; i < 4; ++i) {
        float* p = buf + ((size_t)(b0 + r0 + i) * Tsz + 0) * Hsz + n0 + j;
        *p = fmaxf(*p, 0.f);
    }

    const float* wrow = WsT + j * REC_P;

    for (int t = 1; t < Tsz; ++t) {
        grid_barrier(gen);   // h_{t-1} visible everywhere; also guards Ash reuse

        // Stage h_{t-1} rows b0..b0+31 into smem.
        for (int i = tid; i < 32 * 128; i += 256) {
            int rr = i >> 7;
            int c  = (i & 127) * 4;
            float4 v = *reinterpret_cast<const float4*>(
                buf + ((size_t)(b0 + rr) * Tsz + (t - 1)) * Hsz + c);
            *reinterpret_cast<float4*>(Ash + rr * Hsz + c) = v;
        }
        __syncthreads();

        unsigned long long acc[4]  = {0ull, 0ull, 0ull, 0ull};
        unsigned long long accB[4] = {0ull, 0ull, 0ull, 0ull};

#pragma unroll 4
        for (int k = 0; k < Hsz; k += 8) {
            ulonglong2 w0 = *reinterpret_cast<const ulonglong2*>(wrow + k);
            ulonglong2 w1 = *reinterpret_cast<const ulonglong2*>(wrow + k + 4);
#pragma unroll
            for (int i = 0; i < 4; ++i) {
                const float* xr = Ash + (r0 + i) * Hsz + k;
                ulonglong2 x0 = *reinterpret_cast<const ulonglong2*>(xr);
                ulonglong2 x1 = *reinterpret_cast<const ulonglong2*>(xr + 4);
                acc[i]  = ffma2(x0.x, w0.x, acc[i]);
                accB[i] = ffma2(x0.y, w0.y, accB[i]);
                acc[i]  = ffma2(x1.x, w1.x, acc[i]);
                accB[i] = ffma2(x1.y, w1.y, accB[i]);
            }
        }

        // h_t = relu(proj_t + h_{t-1} @ W^T), in place.
#pragma unroll
        for (int i = 0; i < 4; ++i) {
            float* p = buf + ((size_t)(b0 + r0 + i) * Tsz + t) * Hsz + n0 + j;
            float s = f2sum(acc[i]) + f2sum(accB[i]);
            *p = fmaxf(*p + s, 0.f);
        }
        // No per-thread fence: next barrier's tid0 fence publishes these stores.
    }
}

// ---------------------------------------------------------------------------
// Final FC: out[b,c] = sum_i flat[b,i] * Wfc[c,i] + bfc[c]
// 128 CTAs; each handles batch rows b and b+128 to halve W_fc traffic.
// ---------------------------------------------------------------------------
__global__ void __launch_bounds__(256) fc_kernel(
    const float* __restrict__ flat, const float* __restrict__ Wfc,
    const float* __restrict__ bfc, float* __restrict__ out)
{
    const int b = blockIdx.x;
    const float* xr0 = flat + (size_t)b * (Tsz * Hsz);
    const float* xr1 = flat + (size_t)(b + 128) * (Tsz * Hsz);

    float acc[2][Csz];
#pragma unroll
    for (int rr = 0; rr < 2; ++rr)
#pragma unroll
        for (int c = 0; c < Csz; ++c) acc[rr][c] = 0.f;

    for (int i = threadIdx.x * 4; i < Tsz * Hsz; i += 256 * 4) {
        float4 x0 = *reinterpret_cast<const float4*>(xr0 + i);
        float4 x1 = *reinterpret_cast<const float4*>(xr1 + i);
#pragma unroll
        for (int c = 0; c < Csz; ++c) {
            float4 w = *reinterpret_cast<const float4*>(
                Wfc + (size_t)c * (Tsz * Hsz) + i);
            acc[0][c] += x0.x * w.x + x0.y * w.y + x0.z * w.z + x0.w * w.w;
            acc[1][c] += x1.x * w.x + x1.y * w.y + x1.z * w.z + x1.w * w.w;
        }
    }

#pragma unroll
    for (int rr = 0; rr < 2; ++rr)
#pragma unroll
        for (int c = 0; c < Csz; ++c)
#pragma unroll
            for (int off = 16; off > 0; off >>= 1)
                acc[rr][c] += __shfl_down_sync(0xffffffffu, acc[rr][c], off);

    __shared__ float part[2][Csz][8];
    const int warp = threadIdx.x >> 5;
    const int lane = threadIdx.x & 31;
    if (lane == 0) {
#pragma unroll
        for (int rr = 0; rr < 2; ++rr)
#pragma unroll
            for (int c = 0; c < Csz; ++c) part[rr][c][warp] = acc[rr][c];
    }
    __syncthreads();
    if (threadIdx.x < 2 * Csz) {
        int rr = threadIdx.x / Csz;
        int c  = threadIdx.x % Csz;
        float s = 0.f;
#pragma unroll
        for (int w = 0; w < 8; ++w) s += part[rr][c][w];
        out[(b + rr * 128) * Csz + c] = s + bfc[c];
    }
}

// ---------------------------------------------------------------------------
// kernel_launch: proj0 -> rec0 -> proj1 -> rec1 -> fc  (default stream)
// ---------------------------------------------------------------------------
extern "C" void kernel_launch(void* const* d_in, const int* in_sizes, int n_in,
                              void* d_out, int out_size)
{
    (void)in_sizes; (void)n_in; (void)out_size;
    const float* x     = (const float*)d_in[0];
    const float* W_ih0 = (const float*)d_in[1];
    const float* W_hh0 = (const float*)d_in[2];
    const float* b_ih0 = (const float*)d_in[3];
    const float* b_hh0 = (const float*)d_in[4];
    const float* W_ih1 = (const float*)d_in[5];
    const float* W_hh1 = (const float*)d_in[6];
    const float* b_ih1 = (const float*)d_in[7];
    const float* b_hh1 = (const float*)d_in[8];
    const float* W_fc  = (const float*)d_in[9];
    const float* b_fc  = (const float*)d_in[10];
    float* out = (float*)d_out;

    float* buf0 = nullptr;
    float* buf1 = nullptr;
    cudaGetSymbolAddress((void**)&buf0, g_buf0);
    cudaGetSymbolAddress((void**)&buf1, g_buf1);

    cudaFuncSetAttribute(rnn_rec, cudaFuncAttributeMaxDynamicSharedMemorySize,
                         REC_SMEM_BYTES);

    dim3 pgrid(Hsz / PJ_BN, (Bsz * Tsz) / PJ_BM);   // (8, 256)

    // Layer 0
    proj_gemm<<<pgrid, 256>>>(x, W_ih0, b_ih0, b_hh0, buf0, Fsz);
    rnn_rec<<<REC_NBLK, 256, REC_SMEM_BYTES>>>(buf0, W_hh0);

    // Layer 1
    proj_gemm<<<pgrid, 256>>>(buf0, W_ih1, b_ih1, b_hh1, buf1, Hsz);
    rnn_rec<<<REC_NBLK, 256, REC_SMEM_BYTES>>>(buf1, W_hh1);

    // Classifier
    fc_kernel<<<128, 256>>>(buf1, W_fc, b_fc, out);
}